// round 15
// baseline (speedup 1.0000x reference)
#include <cuda_runtime.h>
#include <cuda_fp16.h>
#include <cstdint>

#define N_ROWS 16384
#define DIM    256
#define TILE_M 256
#define TILE_N 256
#define THREADS 512
#define CHUNK_K 64                        // K split into 4 chunks of 64
#define N_CHUNKS (DIM / CHUNK_K)          // 4
#define ROW_BYTES (CHUNK_K*2 + 16)        // 144 B padded row stride (conflict-free ldmatrix)
#define CHUNK_BYTES_A (TILE_M * ROW_BYTES)    // 36864
#define CHUNK_BYTES_B (TILE_N * ROW_BYTES)    // 36864

// dynamic smem layout (2-stage double buffer)
#define SMEM_KEY  0                       // 512 u32 keys (256 row + 256 col)
#define SMEM_A    2048
#define SMEM_B    (SMEM_A + 2*CHUNK_BYTES_A)
#define SMEM_TOTAL (SMEM_B + 2*CHUNK_BYTES_B)   // 149504 B -> 1 CTA/SM (16 warps = 4/SMSP)

#define ENT_BLOCKS 64

__device__ __align__(16) __half g_Xn[N_ROWS*DIM];
__device__ __align__(16) __half g_Yn[N_ROWS*DIM];
__device__ unsigned g_rowmax[N_ROWS];
__device__ unsigned g_colmax[N_ROWS];
__device__ float g_part1[ENT_BLOCKS];
__device__ float g_part2[ENT_BLOCKS];
__device__ unsigned g_ent_ctr = 0;

static __device__ __forceinline__ uint32_t smem_u32(const void* p){
    uint32_t a;
    asm("{ .reg .u64 t; cvta.to.shared.u64 t, %1; cvt.u32.u64 %0, t; }" : "=r"(a) : "l"(p));
    return a;
}
// monotone float -> unsigned key (atomicMax over floats incl. negatives)
static __device__ __forceinline__ unsigned f2key(float f){
    unsigned b = __float_as_uint(f);
    return b ^ ((unsigned)((int)b >> 31) | 0x80000000u);
}
static __device__ __forceinline__ float key2f(unsigned k){
    unsigned b = (k & 0x80000000u) ? (k ^ 0x80000000u) : ~k;
    return __uint_as_float(b);
}
static __device__ __forceinline__ void cp_async16(uint32_t dst, const void* src){
    asm volatile("cp.async.cg.shared.global [%0], [%1], 16;" :: "r"(dst), "l"(src) : "memory");
}
static __device__ __forceinline__ void ldm_x4(uint32_t* r, uint32_t addr){
    asm volatile("ldmatrix.sync.aligned.m8n8.x4.shared.b16 {%0,%1,%2,%3}, [%4];"
        : "=r"(r[0]), "=r"(r[1]), "=r"(r[2]), "=r"(r[3]) : "r"(addr));
}
// fp16 inputs, fp16 accumulators (best measured rate on sm_103 legacy pipe)
static __device__ __forceinline__ void mma16816_f16(uint32_t* c, const uint32_t* a,
                                                    uint32_t b0, uint32_t b1){
    asm volatile(
        "mma.sync.aligned.m16n8k16.row.col.f16.f16.f16.f16 "
        "{%0,%1}, {%2,%3,%4,%5}, {%6,%7}, {%0,%1};"
        : "+r"(c[0]), "+r"(c[1])
        : "r"(a[0]), "r"(a[1]), "r"(a[2]), "r"(a[3]), "r"(b0), "r"(b1));
}
static __device__ __forceinline__ float half_lo(uint32_t r){
    return __low2float(*reinterpret_cast<__half2*>(&r));
}
static __device__ __forceinline__ float half_hi(uint32_t r){
    return __high2float(*reinterpret_cast<__half2*>(&r));
}

// ---------------------------------------------------------------------------
// Kernel 1: row-normalize ex/ey to fp16 (1 row per warp — measured-best);
// zero the max-key arrays; reset entropy counter.
// ---------------------------------------------------------------------------
__global__ void __launch_bounds__(256) normalize_kernel(
    const float* __restrict__ ex, const float* __restrict__ ey)
{
    const int tid = threadIdx.x, wid = tid >> 5, lid = tid & 31;
    const int g = blockIdx.x * 256 + tid;
    if (g < N_ROWS)            g_rowmax[g] = 0u;
    else if (g < 2 * N_ROWS)   g_colmax[g - N_ROWS] = 0u;
    if (g == 0)                g_ent_ctr = 0u;

    const int r = blockIdx.x * 8 + wid;
    const float* src; __half* dst; int row;
    if (r < N_ROWS) { src = ex; row = r;          dst = g_Xn; }
    else            { src = ey; row = r - N_ROWS; dst = g_Yn; }

    const float4* p = reinterpret_cast<const float4*>(src + (size_t)row * DIM);
    float4 a = p[lid * 2], b = p[lid * 2 + 1];
    float ss = a.x*a.x + a.y*a.y + a.z*a.z + a.w*a.w
             + b.x*b.x + b.y*b.y + b.z*b.z + b.w*b.w;
    #pragma unroll
    for (int o = 16; o; o >>= 1) ss += __shfl_xor_sync(0xFFFFFFFFu, ss, o);
    float inv = 1.0f / fmaxf(sqrtf(ss), 1e-8f);

    __half2 h0 = __floats2half2_rn(a.x*inv, a.y*inv);
    __half2 h1 = __floats2half2_rn(a.z*inv, a.w*inv);
    __half2 h2 = __floats2half2_rn(b.x*inv, b.y*inv);
    __half2 h3 = __floats2half2_rn(b.z*inv, b.w*inv);
    uint4 o4;
    o4.x = *reinterpret_cast<unsigned*>(&h0);
    o4.y = *reinterpret_cast<unsigned*>(&h1);
    o4.z = *reinterpret_cast<unsigned*>(&h2);
    o4.w = *reinterpret_cast<unsigned*>(&h3);
    reinterpret_cast<uint4*>(dst + (size_t)row * DIM)[lid] = o4;
}

// ---------------------------------------------------------------------------
// Kernel 2: 256x256xK256 fp16 HMMA GEMM tile (D = Xn @ Yn^T) with in-epilogue
// row/col max reduction. 16 warps (4 m x 4 n), warp tile 64x64.
// fp16 acc; 2-stage cp.async buffer; 1 CTA/SM (4 warps/SMSP preserved).
// ---------------------------------------------------------------------------
__global__ void __launch_bounds__(THREADS, 1) gemm_max_kernel()
{
    extern __shared__ char smem[];
    const uint32_t sb = smem_u32(smem);
    const int tid = threadIdx.x, wid = tid >> 5, lid = tid & 31;
    const int warp_m = wid & 3, warp_n = wid >> 2;
    const int m0 = blockIdx.y * TILE_M;
    const int n0 = blockIdx.x * TILE_N;
    unsigned* sKey = reinterpret_cast<unsigned*>(smem + SMEM_KEY);

    sKey[tid] = 0u;

    // prefetch chunk c into stage buffer (c & 1): A 256x64 + B 256x64 fp16
    auto prefetch = [&](int c) {
        const int buf = c & 1;
        #pragma unroll
        for (int u = 0; u < 4; u++) {
            int unit = tid + u * THREADS;              // 0..2047 (A)
            int row = unit >> 3, cu = unit & 7;        // 8 x 16B units per row
            cp_async16(sb + SMEM_A + buf * CHUNK_BYTES_A + row * ROW_BYTES + cu * 16,
                       (const char*)g_Xn + ((size_t)(m0 + row) * DIM + c * CHUNK_K) * 2 + cu * 16);
        }
        #pragma unroll
        for (int u = 0; u < 4; u++) {
            int unit = tid + u * THREADS;              // 0..2047 (B)
            int row = unit >> 3, cu = unit & 7;
            cp_async16(sb + SMEM_B + buf * CHUNK_BYTES_B + row * ROW_BYTES + cu * 16,
                       (const char*)g_Yn + ((size_t)(n0 + row) * DIM + c * CHUNK_K) * 2 + cu * 16);
        }
        asm volatile("cp.async.commit_group;" ::: "memory");
    };

    prefetch(0);
    prefetch(1);

    uint32_t acc[4][8][2];                // fp16x2 accumulators, 64 regs
    #pragma unroll
    for (int mi = 0; mi < 4; mi++)
        #pragma unroll
        for (int ni = 0; ni < 8; ni++) { acc[mi][ni][0] = 0u; acc[mi][ni][1] = 0u; }

    const uint32_t lrow = (lid & 15), lcol16 = (lid >> 4) * 16;

    #pragma unroll
    for (int c = 0; c < N_CHUNKS; c++) {
        if (c < N_CHUNKS - 1) asm volatile("cp.async.wait_group 1;" ::: "memory");
        else                  asm volatile("cp.async.wait_group 0;" ::: "memory");
        __syncthreads();

        const uint32_t aBase = sb + SMEM_A + (c & 1) * CHUNK_BYTES_A
                             + (warp_m * 64 + lrow) * ROW_BYTES + lcol16;
        const uint32_t bBase = sb + SMEM_B + (c & 1) * CHUNK_BYTES_B
                             + (warp_n * 64 + lrow) * ROW_BYTES + lcol16;

        #pragma unroll
        for (int kk = 0; kk < CHUNK_K / 16; kk++) {
            uint32_t a[4][4], b[4][4];
            #pragma unroll
            for (int mi = 0; mi < 4; mi++)
                ldm_x4(a[mi], aBase + mi * 16 * ROW_BYTES + kk * 32);
            #pragma unroll
            for (int nb = 0; nb < 4; nb++)
                ldm_x4(b[nb], bBase + nb * 16 * ROW_BYTES + kk * 32);
            #pragma unroll
            for (int mi = 0; mi < 4; mi++)
                #pragma unroll
                for (int ni = 0; ni < 8; ni++)
                    mma16816_f16(acc[mi][ni], a[mi], b[ni >> 1][ni & 1], b[ni >> 1][(ni & 1) + 2]);
        }
        __syncthreads();
        if (c + 2 < N_CHUNKS) prefetch(c + 2);
    }

    // --- epilogue: row max -----------------------------------------------
    // acc[mi][ni][h]: u32 = 2 halves {col even, col odd}
    //   row = warp_m*64 + mi*16 + h*8 + (lid>>2)
    //   col = warp_n*64 + ni*8 + (lid&3)*2 + {0,1}
    #pragma unroll
    for (int mi = 0; mi < 4; mi++) {
        #pragma unroll
        for (int h = 0; h < 2; h++) {
            float rm = -2.0f;
            #pragma unroll
            for (int ni = 0; ni < 8; ni++)
                rm = fmaxf(rm, fmaxf(half_lo(acc[mi][ni][h]), half_hi(acc[mi][ni][h])));
            rm = fmaxf(rm, __shfl_xor_sync(0xFFFFFFFFu, rm, 1));
            rm = fmaxf(rm, __shfl_xor_sync(0xFFFFFFFFu, rm, 2));
            if ((lid & 3) == 0)
                atomicMax(&sKey[warp_m * 64 + mi * 16 + h * 8 + (lid >> 2)], f2key(rm));
        }
    }
    // --- col max ---------------------------------------------------------
    #pragma unroll
    for (int ni = 0; ni < 8; ni++) {
        #pragma unroll
        for (int p = 0; p < 2; p++) {
            float cm = -2.0f;
            #pragma unroll
            for (int mi = 0; mi < 4; mi++) {
                float v0 = p ? half_hi(acc[mi][ni][0]) : half_lo(acc[mi][ni][0]);
                float v1 = p ? half_hi(acc[mi][ni][1]) : half_lo(acc[mi][ni][1]);
                cm = fmaxf(cm, fmaxf(v0, v1));
            }
            cm = fmaxf(cm, __shfl_xor_sync(0xFFFFFFFFu, cm, 4));
            cm = fmaxf(cm, __shfl_xor_sync(0xFFFFFFFFu, cm, 8));
            cm = fmaxf(cm, __shfl_xor_sync(0xFFFFFFFFu, cm, 16));
            if (lid < 4)
                atomicMax(&sKey[256 + warp_n * 64 + ni * 8 + lid * 2 + p], f2key(cm));
        }
    }
    __syncthreads();

    if (tid < 256) atomicMax(&g_rowmax[m0 + tid], sKey[tid]);
    else           atomicMax(&g_colmax[n0 + tid - 256], sKey[tid]);
}

// ---------------------------------------------------------------------------
// Kernel 3: fused entropy reduction. 64 blocks produce deterministic partial
// sums; the last-arriving block folds all partials and writes out[0..1].
// ---------------------------------------------------------------------------
__global__ void __launch_bounds__(256) entropy_kernel(float* __restrict__ out)
{
    __shared__ float red[256];
    __shared__ unsigned sLast;
    const int t = threadIdx.x;
    const int i = blockIdx.x * 256 + t;
    const float A = 5.5555555556f;      // 1/(2*sigma^2), sigma=0.3
    const float B = 0.28503426769f;     // -(log(0.3)+0.5*log(2*pi))

    float v = key2f(g_rowmax[i]);
    float d = v - 1.0f;
    float lp = B - A * d * d;
    float s1 = -expf(lp) * lp;

    v = key2f(g_colmax[i]);
    d = v - 1.0f;
    lp = B - A * d * d;
    float s2 = -expf(lp) * lp;

    red[t] = s1; __syncthreads();
    for (int o = 128; o; o >>= 1) { if (t < o) red[t] += red[t + o]; __syncthreads(); }
    if (t == 0) g_part1[blockIdx.x] = red[0];
    __syncthreads();
    red[t] = s2; __syncthreads();
    for (int o = 128; o; o >>= 1) { if (t < o) red[t] += red[t + o]; __syncthreads(); }
    if (t == 0) {
        g_part2[blockIdx.x] = red[0];
        __threadfence();
        sLast = (atomicAdd(&g_ent_ctr, 1u) == ENT_BLOCKS - 1);
    }
    __syncthreads();

    if (sLast) {
        __threadfence();                  // order partial reads after counter
        if (t < 64) {
            const int lid = t & 31;
            float x = (t < 32) ? g_part1[lid] + g_part1[lid + 32]
                               : g_part2[lid] + g_part2[lid + 32];
            #pragma unroll
            for (int o = 16; o; o >>= 1) x += __shfl_xor_sync(0xFFFFFFFFu, x, o);
            if (lid == 0) out[t >> 5] = x;
        }
        if (t == 0) g_ent_ctr = 0u;       // reset for next graph replay
    }
}

extern "C" void kernel_launch(void* const* d_in, const int* in_sizes, int n_in,
                              void* d_out, int out_size)
{
    const float* ex = (const float*)d_in[0];
    const float* ey = (const float*)d_in[1];
    float* out = (float*)d_out;

    cudaFuncSetAttribute(gemm_max_kernel,
                         cudaFuncAttributeMaxDynamicSharedMemorySize, SMEM_TOTAL);

    normalize_kernel<<<(2 * N_ROWS) / 8, 256>>>(ex, ey);
    gemm_max_kernel<<<dim3(N_ROWS / TILE_N, N_ROWS / TILE_M), THREADS, SMEM_TOTAL>>>();
    entropy_kernel<<<ENT_BLOCKS, 256>>>(out);
}

// round 16
// speedup vs baseline: 1.0855x; 1.0855x over previous
#include <cuda_runtime.h>
#include <cuda_fp16.h>
#include <cstdint>

#define N_ROWS 16384
#define DIM    256
#define TILE_M 128
#define TILE_N 256
#define CHUNK_K 64                        // K split into 4 chunks of 64
#define N_CHUNKS (DIM / CHUNK_K)          // 4
#define ROW_BYTES (CHUNK_K*2 + 16)        // 144 B padded row stride (conflict-free ldmatrix)
#define CHUNK_BYTES_A (TILE_M * ROW_BYTES)    // 18432
#define CHUNK_BYTES_B (TILE_N * ROW_BYTES)    // 36864

// dynamic smem layout (2-stage double buffer)
#define SMEM_KEY  0                       // 384 u32 keys (128 row + 256 col)
#define SMEM_A    2048
#define SMEM_B    (SMEM_A + 2*CHUNK_BYTES_A)
#define SMEM_TOTAL (SMEM_B + 2*CHUNK_BYTES_B)   // 112640 B -> 2 CTAs/SM

#define ENT_BLOCKS 64

__device__ __align__(16) __half g_Xn[N_ROWS*DIM];
__device__ __align__(16) __half g_Yn[N_ROWS*DIM];
__device__ unsigned g_rowmax[N_ROWS];
__device__ unsigned g_colmax[N_ROWS];
__device__ float g_part1[ENT_BLOCKS];
__device__ float g_part2[ENT_BLOCKS];
__device__ unsigned g_ent_ctr = 0;

static __device__ __forceinline__ uint32_t smem_u32(const void* p){
    uint32_t a;
    asm("{ .reg .u64 t; cvta.to.shared.u64 t, %1; cvt.u32.u64 %0, t; }" : "=r"(a) : "l"(p));
    return a;
}
// monotone float -> unsigned key (atomicMax over floats incl. negatives)
static __device__ __forceinline__ unsigned f2key(float f){
    unsigned b = __float_as_uint(f);
    return b ^ ((unsigned)((int)b >> 31) | 0x80000000u);
}
static __device__ __forceinline__ float key2f(unsigned k){
    unsigned b = (k & 0x80000000u) ? (k ^ 0x80000000u) : ~k;
    return __uint_as_float(b);
}
static __device__ __forceinline__ void cp_async16(uint32_t dst, const void* src){
    asm volatile("cp.async.cg.shared.global [%0], [%1], 16;" :: "r"(dst), "l"(src) : "memory");
}
static __device__ __forceinline__ void ldm_x4(uint32_t* r, uint32_t addr){
    asm volatile("ldmatrix.sync.aligned.m8n8.x4.shared.b16 {%0,%1,%2,%3}, [%4];"
        : "=r"(r[0]), "=r"(r[1]), "=r"(r[2]), "=r"(r[3]) : "r"(addr));
}
// fp16 inputs, fp16 accumulators (best measured rate on sm_103 legacy pipe)
static __device__ __forceinline__ void mma16816_f16(uint32_t* c, const uint32_t* a,
                                                    uint32_t b0, uint32_t b1){
    asm volatile(
        "mma.sync.aligned.m16n8k16.row.col.f16.f16.f16.f16 "
        "{%0,%1}, {%2,%3,%4,%5}, {%6,%7}, {%0,%1};"
        : "+r"(c[0]), "+r"(c[1])
        : "r"(a[0]), "r"(a[1]), "r"(a[2]), "r"(a[3]), "r"(b0), "r"(b1));
}
static __device__ __forceinline__ float half_lo(uint32_t r){
    return __low2float(*reinterpret_cast<__half2*>(&r));
}
static __device__ __forceinline__ float half_hi(uint32_t r){
    return __high2float(*reinterpret_cast<__half2*>(&r));
}

// ---------------------------------------------------------------------------
// Kernel 1: row-normalize ex/ey to fp16 (1 row per warp — measured-best);
// zero the max-key arrays; reset entropy counter.
// ---------------------------------------------------------------------------
__global__ void __launch_bounds__(256) normalize_kernel(
    const float* __restrict__ ex, const float* __restrict__ ey)
{
    const int tid = threadIdx.x, wid = tid >> 5, lid = tid & 31;
    const int g = blockIdx.x * 256 + tid;
    if (g < N_ROWS)            g_rowmax[g] = 0u;
    else if (g < 2 * N_ROWS)   g_colmax[g - N_ROWS] = 0u;
    if (g == 0)                g_ent_ctr = 0u;

    const int r = blockIdx.x * 8 + wid;
    const float* src; __half* dst; int row;
    if (r < N_ROWS) { src = ex; row = r;          dst = g_Xn; }
    else            { src = ey; row = r - N_ROWS; dst = g_Yn; }

    const float4* p = reinterpret_cast<const float4*>(src + (size_t)row * DIM);
    float4 a = p[lid * 2], b = p[lid * 2 + 1];
    float ss = a.x*a.x + a.y*a.y + a.z*a.z + a.w*a.w
             + b.x*b.x + b.y*b.y + b.z*b.z + b.w*b.w;
    #pragma unroll
    for (int o = 16; o; o >>= 1) ss += __shfl_xor_sync(0xFFFFFFFFu, ss, o);
    float inv = 1.0f / fmaxf(sqrtf(ss), 1e-8f);

    __half2 h0 = __floats2half2_rn(a.x*inv, a.y*inv);
    __half2 h1 = __floats2half2_rn(a.z*inv, a.w*inv);
    __half2 h2 = __floats2half2_rn(b.x*inv, b.y*inv);
    __half2 h3 = __floats2half2_rn(b.z*inv, b.w*inv);
    uint4 o4;
    o4.x = *reinterpret_cast<unsigned*>(&h0);
    o4.y = *reinterpret_cast<unsigned*>(&h1);
    o4.z = *reinterpret_cast<unsigned*>(&h2);
    o4.w = *reinterpret_cast<unsigned*>(&h3);
    reinterpret_cast<uint4*>(dst + (size_t)row * DIM)[lid] = o4;
}

// ---------------------------------------------------------------------------
// Kernel 2: 128x256xK256 fp16 HMMA GEMM tile (D = Xn @ Yn^T) with in-epilogue
// row/col max reduction. 8 warps (2 m x 4 n), warp tile 64x64 (measured-best
// crossbar/latency tradeoff). fp16 acc; 2-stage cp.async buffer; 2 CTAs/SM.
// ---------------------------------------------------------------------------
__global__ void __launch_bounds__(256, 2) gemm_max_kernel()
{
    extern __shared__ char smem[];
    const uint32_t sb = smem_u32(smem);
    const int tid = threadIdx.x, wid = tid >> 5, lid = tid & 31;
    const int warp_m = wid & 1, warp_n = wid >> 1;
    const int m0 = blockIdx.y * TILE_M;
    const int n0 = blockIdx.x * TILE_N;
    unsigned* sKey = reinterpret_cast<unsigned*>(smem + SMEM_KEY);

    sKey[tid] = 0u;
    if (tid < 128) sKey[256 + tid] = 0u;

    // prefetch chunk c into stage buffer (c & 1): A 128x64 + B 256x64 fp16
    auto prefetch = [&](int c) {
        const int buf = c & 1;
        #pragma unroll
        for (int u = 0; u < 4; u++) {
            int unit = tid + u * 256;                  // 0..1023 (A)
            int row = unit >> 3, cu = unit & 7;        // 8 x 16B units per row
            cp_async16(sb + SMEM_A + buf * CHUNK_BYTES_A + row * ROW_BYTES + cu * 16,
                       (const char*)g_Xn + ((size_t)(m0 + row) * DIM + c * CHUNK_K) * 2 + cu * 16);
        }
        #pragma unroll
        for (int u = 0; u < 8; u++) {
            int unit = tid + u * 256;                  // 0..2047 (B)
            int row = unit >> 3, cu = unit & 7;
            cp_async16(sb + SMEM_B + buf * CHUNK_BYTES_B + row * ROW_BYTES + cu * 16,
                       (const char*)g_Yn + ((size_t)(n0 + row) * DIM + c * CHUNK_K) * 2 + cu * 16);
        }
        asm volatile("cp.async.commit_group;" ::: "memory");
    };

    prefetch(0);
    prefetch(1);

    uint32_t acc[4][8][2];                // fp16x2 accumulators, 64 regs
    #pragma unroll
    for (int mi = 0; mi < 4; mi++)
        #pragma unroll
        for (int ni = 0; ni < 8; ni++) { acc[mi][ni][0] = 0u; acc[mi][ni][1] = 0u; }

    const uint32_t lrow = (lid & 15), lcol16 = (lid >> 4) * 16;

    #pragma unroll
    for (int c = 0; c < N_CHUNKS; c++) {
        if (c < N_CHUNKS - 1) asm volatile("cp.async.wait_group 1;" ::: "memory");
        else                  asm volatile("cp.async.wait_group 0;" ::: "memory");
        __syncthreads();

        const uint32_t aBase = sb + SMEM_A + (c & 1) * CHUNK_BYTES_A
                             + (warp_m * 64 + lrow) * ROW_BYTES + lcol16;
        const uint32_t bBase = sb + SMEM_B + (c & 1) * CHUNK_BYTES_B
                             + (warp_n * 64 + lrow) * ROW_BYTES + lcol16;

        #pragma unroll
        for (int kk = 0; kk < CHUNK_K / 16; kk++) {
            uint32_t a[4][4], b[4][4];
            #pragma unroll
            for (int mi = 0; mi < 4; mi++)
                ldm_x4(a[mi], aBase + mi * 16 * ROW_BYTES + kk * 32);
            #pragma unroll
            for (int nb = 0; nb < 4; nb++)
                ldm_x4(b[nb], bBase + nb * 16 * ROW_BYTES + kk * 32);
            #pragma unroll
            for (int mi = 0; mi < 4; mi++)
                #pragma unroll
                for (int ni = 0; ni < 8; ni++)
                    mma16816_f16(acc[mi][ni], a[mi], b[ni >> 1][ni & 1], b[ni >> 1][(ni & 1) + 2]);
        }
        __syncthreads();
        if (c + 2 < N_CHUNKS) prefetch(c + 2);
    }

    // --- epilogue: row max -----------------------------------------------
    // acc[mi][ni][h]: u32 = 2 halves {col even, col odd}
    //   row = warp_m*64 + mi*16 + h*8 + (lid>>2)
    //   col = warp_n*64 + ni*8 + (lid&3)*2 + {0,1}
    #pragma unroll
    for (int mi = 0; mi < 4; mi++) {
        #pragma unroll
        for (int h = 0; h < 2; h++) {
            float rm = -2.0f;
            #pragma unroll
            for (int ni = 0; ni < 8; ni++)
                rm = fmaxf(rm, fmaxf(half_lo(acc[mi][ni][h]), half_hi(acc[mi][ni][h])));
            rm = fmaxf(rm, __shfl_xor_sync(0xFFFFFFFFu, rm, 1));
            rm = fmaxf(rm, __shfl_xor_sync(0xFFFFFFFFu, rm, 2));
            if ((lid & 3) == 0)
                atomicMax(&sKey[warp_m * 64 + mi * 16 + h * 8 + (lid >> 2)], f2key(rm));
        }
    }
    // --- col max ---------------------------------------------------------
    #pragma unroll
    for (int ni = 0; ni < 8; ni++) {
        #pragma unroll
        for (int p = 0; p < 2; p++) {
            float cm = -2.0f;
            #pragma unroll
            for (int mi = 0; mi < 4; mi++) {
                float v0 = p ? half_hi(acc[mi][ni][0]) : half_lo(acc[mi][ni][0]);
                float v1 = p ? half_hi(acc[mi][ni][1]) : half_lo(acc[mi][ni][1]);
                cm = fmaxf(cm, fmaxf(v0, v1));
            }
            cm = fmaxf(cm, __shfl_xor_sync(0xFFFFFFFFu, cm, 4));
            cm = fmaxf(cm, __shfl_xor_sync(0xFFFFFFFFu, cm, 8));
            cm = fmaxf(cm, __shfl_xor_sync(0xFFFFFFFFu, cm, 16));
            if (lid < 4)
                atomicMax(&sKey[128 + warp_n * 64 + ni * 8 + lid * 2 + p], f2key(cm));
        }
    }
    __syncthreads();

    if (tid < 128) atomicMax(&g_rowmax[m0 + tid], sKey[tid]);
    atomicMax(&g_colmax[n0 + tid], sKey[128 + tid]);
}

// ---------------------------------------------------------------------------
// Kernel 3: fused entropy reduction. 64 blocks produce deterministic partial
// sums; the last-arriving block folds all partials and writes out[0..1].
// ---------------------------------------------------------------------------
__global__ void __launch_bounds__(256) entropy_kernel(float* __restrict__ out)
{
    __shared__ float red[256];
    __shared__ unsigned sLast;
    const int t = threadIdx.x;
    const int i = blockIdx.x * 256 + t;
    const float A = 5.5555555556f;      // 1/(2*sigma^2), sigma=0.3
    const float B = 0.28503426769f;     // -(log(0.3)+0.5*log(2*pi))

    float v = key2f(g_rowmax[i]);
    float d = v - 1.0f;
    float lp = B - A * d * d;
    float s1 = -expf(lp) * lp;

    v = key2f(g_colmax[i]);
    d = v - 1.0f;
    lp = B - A * d * d;
    float s2 = -expf(lp) * lp;

    red[t] = s1; __syncthreads();
    for (int o = 128; o; o >>= 1) { if (t < o) red[t] += red[t + o]; __syncthreads(); }
    if (t == 0) g_part1[blockIdx.x] = red[0];
    __syncthreads();
    red[t] = s2; __syncthreads();
    for (int o = 128; o; o >>= 1) { if (t < o) red[t] += red[t + o]; __syncthreads(); }
    if (t == 0) {
        g_part2[blockIdx.x] = red[0];
        __threadfence();
        sLast = (atomicAdd(&g_ent_ctr, 1u) == ENT_BLOCKS - 1);
    }
    __syncthreads();

    if (sLast) {
        __threadfence();                  // order partial reads after counter
        if (t < 64) {
            const int lid = t & 31;
            float x = (t < 32) ? g_part1[lid] + g_part1[lid + 32]
                               : g_part2[lid] + g_part2[lid + 32];
            #pragma unroll
            for (int o = 16; o; o >>= 1) x += __shfl_xor_sync(0xFFFFFFFFu, x, o);
            if (lid == 0) out[t >> 5] = x;
        }
        if (t == 0) g_ent_ctr = 0u;       // reset for next graph replay
    }
}

extern "C" void kernel_launch(void* const* d_in, const int* in_sizes, int n_in,
                              void* d_out, int out_size)
{
    const float* ex = (const float*)d_in[0];
    const float* ey = (const float*)d_in[1];
    float* out = (float*)d_out;

    cudaFuncSetAttribute(gemm_max_kernel,
                         cudaFuncAttributeMaxDynamicSharedMemorySize, SMEM_TOTAL);

    normalize_kernel<<<(2 * N_ROWS) / 8, 256>>>(ex, ey);
    gemm_max_kernel<<<dim3(N_ROWS / TILE_N, N_ROWS / TILE_M), 256, SMEM_TOTAL>>>();
    entropy_kernel<<<ENT_BLOCKS, 256>>>(out);
}

// round 17
// speedup vs baseline: 1.1040x; 1.0170x over previous
#include <cuda_runtime.h>
#include <cuda_fp16.h>
#include <cstdint>

#define N_ROWS 16384
#define DIM    256
#define TILE_M 128
#define TILE_N 256
#define CHUNK_K 64                        // K split into 4 chunks of 64
#define N_CHUNKS (DIM / CHUNK_K)          // 4
#define ROW_BYTES (CHUNK_K*2 + 16)        // 144 B padded row stride (conflict-free ldmatrix)
#define CHUNK_BYTES_A (TILE_M * ROW_BYTES)    // 18432
#define CHUNK_BYTES_B (TILE_N * ROW_BYTES)    // 36864

// dynamic smem layout (2-stage double buffer)
#define SMEM_KEY  0                       // 384 u32 keys (128 row + 256 col)
#define SMEM_A    2048
#define SMEM_B    (SMEM_A + 2*CHUNK_BYTES_A)
#define SMEM_TOTAL (SMEM_B + 2*CHUNK_BYTES_B)   // 112640 B -> 2 CTAs/SM

#define ENT_BLOCKS 64

__device__ __align__(16) __half g_Xn[N_ROWS*DIM];
__device__ __align__(16) __half g_Yn[N_ROWS*DIM];
__device__ unsigned g_rowmax[N_ROWS];
__device__ unsigned g_colmax[N_ROWS];
__device__ float g_part1[ENT_BLOCKS];
__device__ float g_part2[ENT_BLOCKS];
__device__ unsigned g_ent_ctr = 0;

static __device__ __forceinline__ uint32_t smem_u32(const void* p){
    uint32_t a;
    asm("{ .reg .u64 t; cvta.to.shared.u64 t, %1; cvt.u32.u64 %0, t; }" : "=r"(a) : "l"(p));
    return a;
}
// monotone float -> unsigned key (atomicMax over floats incl. negatives)
static __device__ __forceinline__ unsigned f2key(float f){
    unsigned b = __float_as_uint(f);
    return b ^ ((unsigned)((int)b >> 31) | 0x80000000u);
}
static __device__ __forceinline__ float key2f(unsigned k){
    unsigned b = (k & 0x80000000u) ? (k ^ 0x80000000u) : ~k;
    return __uint_as_float(b);
}
static __device__ __forceinline__ void cp_async16(uint32_t dst, const void* src){
    asm volatile("cp.async.cg.shared.global [%0], [%1], 16;" :: "r"(dst), "l"(src) : "memory");
}
static __device__ __forceinline__ void ldm_x4(uint32_t* r, uint32_t addr){
    asm volatile("ldmatrix.sync.aligned.m8n8.x4.shared.b16 {%0,%1,%2,%3}, [%4];"
        : "=r"(r[0]), "=r"(r[1]), "=r"(r[2]), "=r"(r[3]) : "r"(addr));
}
// fp16 inputs, fp16 accumulators (best measured rate on sm_103 legacy pipe)
static __device__ __forceinline__ void mma16816_f16(uint32_t* c, const uint32_t* a,
                                                    uint32_t b0, uint32_t b1){
    asm volatile(
        "mma.sync.aligned.m16n8k16.row.col.f16.f16.f16.f16 "
        "{%0,%1}, {%2,%3,%4,%5}, {%6,%7}, {%0,%1};"
        : "+r"(c[0]), "+r"(c[1])
        : "r"(a[0]), "r"(a[1]), "r"(a[2]), "r"(a[3]), "r"(b0), "r"(b1));
}
static __device__ __forceinline__ __half2 u2h2(uint32_t r){
    return *reinterpret_cast<__half2*>(&r);
}

// ---------------------------------------------------------------------------
// Kernel 1: row-normalize ex/ey to fp16 (1 row per warp — measured-best);
// zero the max-key arrays; reset entropy counter.
// ---------------------------------------------------------------------------
__global__ void __launch_bounds__(256) normalize_kernel(
    const float* __restrict__ ex, const float* __restrict__ ey)
{
    const int tid = threadIdx.x, wid = tid >> 5, lid = tid & 31;
    const int g = blockIdx.x * 256 + tid;
    if (g < N_ROWS)            g_rowmax[g] = 0u;
    else if (g < 2 * N_ROWS)   g_colmax[g - N_ROWS] = 0u;
    if (g == 0)                g_ent_ctr = 0u;

    const int r = blockIdx.x * 8 + wid;
    const float* src; __half* dst; int row;
    if (r < N_ROWS) { src = ex; row = r;          dst = g_Xn; }
    else            { src = ey; row = r - N_ROWS; dst = g_Yn; }

    const float4* p = reinterpret_cast<const float4*>(src + (size_t)row * DIM);
    float4 a = p[lid * 2], b = p[lid * 2 + 1];
    float ss = a.x*a.x + a.y*a.y + a.z*a.z + a.w*a.w
             + b.x*b.x + b.y*b.y + b.z*b.z + b.w*b.w;
    #pragma unroll
    for (int o = 16; o; o >>= 1) ss += __shfl_xor_sync(0xFFFFFFFFu, ss, o);
    float inv = 1.0f / fmaxf(sqrtf(ss), 1e-8f);

    __half2 h0 = __floats2half2_rn(a.x*inv, a.y*inv);
    __half2 h1 = __floats2half2_rn(a.z*inv, a.w*inv);
    __half2 h2 = __floats2half2_rn(b.x*inv, b.y*inv);
    __half2 h3 = __floats2half2_rn(b.z*inv, b.w*inv);
    uint4 o4;
    o4.x = *reinterpret_cast<unsigned*>(&h0);
    o4.y = *reinterpret_cast<unsigned*>(&h1);
    o4.z = *reinterpret_cast<unsigned*>(&h2);
    o4.w = *reinterpret_cast<unsigned*>(&h3);
    reinterpret_cast<uint4*>(dst + (size_t)row * DIM)[lid] = o4;
}

// ---------------------------------------------------------------------------
// Kernel 2: 128x256xK256 fp16 HMMA GEMM tile (D = Xn @ Yn^T) with in-epilogue
// row/col max reduction (packed __hmax2 tree). 8 warps (2 m x 4 n), warp tile
// 64x64. fp16 acc; 2-stage cp.async buffer; 2 CTAs/SM.
// ---------------------------------------------------------------------------
__global__ void __launch_bounds__(256, 2) gemm_max_kernel()
{
    extern __shared__ char smem[];
    const uint32_t sb = smem_u32(smem);
    const int tid = threadIdx.x, wid = tid >> 5, lid = tid & 31;
    const int warp_m = wid & 1, warp_n = wid >> 1;
    const int m0 = blockIdx.y * TILE_M;
    const int n0 = blockIdx.x * TILE_N;
    unsigned* sKey = reinterpret_cast<unsigned*>(smem + SMEM_KEY);

    sKey[tid] = 0u;
    if (tid < 128) sKey[256 + tid] = 0u;

    // prefetch chunk c into stage buffer (c & 1): A 128x64 + B 256x64 fp16
    auto prefetch = [&](int c) {
        const int buf = c & 1;
        #pragma unroll
        for (int u = 0; u < 4; u++) {
            int unit = tid + u * 256;                  // 0..1023 (A)
            int row = unit >> 3, cu = unit & 7;        // 8 x 16B units per row
            cp_async16(sb + SMEM_A + buf * CHUNK_BYTES_A + row * ROW_BYTES + cu * 16,
                       (const char*)g_Xn + ((size_t)(m0 + row) * DIM + c * CHUNK_K) * 2 + cu * 16);
        }
        #pragma unroll
        for (int u = 0; u < 8; u++) {
            int unit = tid + u * 256;                  // 0..2047 (B)
            int row = unit >> 3, cu = unit & 7;
            cp_async16(sb + SMEM_B + buf * CHUNK_BYTES_B + row * ROW_BYTES + cu * 16,
                       (const char*)g_Yn + ((size_t)(n0 + row) * DIM + c * CHUNK_K) * 2 + cu * 16);
        }
        asm volatile("cp.async.commit_group;" ::: "memory");
    };

    prefetch(0);
    prefetch(1);

    uint32_t acc[4][8][2];                // fp16x2 accumulators, 64 regs
    #pragma unroll
    for (int mi = 0; mi < 4; mi++)
        #pragma unroll
        for (int ni = 0; ni < 8; ni++) { acc[mi][ni][0] = 0u; acc[mi][ni][1] = 0u; }

    const uint32_t lrow = (lid & 15), lcol16 = (lid >> 4) * 16;

    #pragma unroll
    for (int c = 0; c < N_CHUNKS; c++) {
        if (c < N_CHUNKS - 1) asm volatile("cp.async.wait_group 1;" ::: "memory");
        else                  asm volatile("cp.async.wait_group 0;" ::: "memory");
        __syncthreads();

        const uint32_t aBase = sb + SMEM_A + (c & 1) * CHUNK_BYTES_A
                             + (warp_m * 64 + lrow) * ROW_BYTES + lcol16;
        const uint32_t bBase = sb + SMEM_B + (c & 1) * CHUNK_BYTES_B
                             + (warp_n * 64 + lrow) * ROW_BYTES + lcol16;

        #pragma unroll
        for (int kk = 0; kk < CHUNK_K / 16; kk++) {
            uint32_t a[4][4], b[4][4];
            #pragma unroll
            for (int mi = 0; mi < 4; mi++)
                ldm_x4(a[mi], aBase + mi * 16 * ROW_BYTES + kk * 32);
            #pragma unroll
            for (int nb = 0; nb < 4; nb++)
                ldm_x4(b[nb], bBase + nb * 16 * ROW_BYTES + kk * 32);
            #pragma unroll
            for (int mi = 0; mi < 4; mi++)
                #pragma unroll
                for (int ni = 0; ni < 8; ni++)
                    mma16816_f16(acc[mi][ni], a[mi], b[ni >> 1][ni & 1], b[ni >> 1][(ni & 1) + 2]);
        }
        __syncthreads();
        if (c + 2 < N_CHUNKS) prefetch(c + 2);
    }

    // --- epilogue: row max (packed __hmax2 tree) --------------------------
    // acc[mi][ni][h]: u32 = 2 halves {col even, col odd}
    //   row = warp_m*64 + mi*16 + h*8 + (lid>>2)
    //   col = warp_n*64 + ni*8 + (lid&3)*2 + {0,1}
    #pragma unroll
    for (int mi = 0; mi < 4; mi++) {
        #pragma unroll
        for (int h = 0; h < 2; h++) {
            __half2 rm2 = u2h2(acc[mi][0][h]);
            #pragma unroll
            for (int ni = 1; ni < 8; ni++)
                rm2 = __hmax2(rm2, u2h2(acc[mi][ni][h]));
            float rm = fmaxf(__low2float(rm2), __high2float(rm2));
            rm = fmaxf(rm, __shfl_xor_sync(0xFFFFFFFFu, rm, 1));
            rm = fmaxf(rm, __shfl_xor_sync(0xFFFFFFFFu, rm, 2));
            if ((lid & 3) == 0)
                atomicMax(&sKey[warp_m * 64 + mi * 16 + h * 8 + (lid >> 2)], f2key(rm));
        }
    }
    // --- col max (packed: lo=even col, hi=odd col) ------------------------
    #pragma unroll
    for (int ni = 0; ni < 8; ni++) {
        __half2 cm2 = __hmax2(u2h2(acc[0][ni][0]), u2h2(acc[0][ni][1]));
        #pragma unroll
        for (int mi = 1; mi < 4; mi++)
            cm2 = __hmax2(cm2, __hmax2(u2h2(acc[mi][ni][0]), u2h2(acc[mi][ni][1])));
        uint32_t cmu = *reinterpret_cast<uint32_t*>(&cm2);
        #pragma unroll
        for (int o = 4; o <= 16; o <<= 1) {
            uint32_t other = __shfl_xor_sync(0xFFFFFFFFu, cmu, o);
            __half2 m = __hmax2(*reinterpret_cast<__half2*>(&cmu),
                                *reinterpret_cast<__half2*>(&other));
            cmu = *reinterpret_cast<uint32_t*>(&m);
        }
        if (lid < 4) {
            __half2 m = *reinterpret_cast<__half2*>(&cmu);
            atomicMax(&sKey[128 + warp_n * 64 + ni * 8 + lid * 2],     f2key(__low2float(m)));
            atomicMax(&sKey[128 + warp_n * 64 + ni * 8 + lid * 2 + 1], f2key(__high2float(m)));
        }
    }
    __syncthreads();

    if (tid < 128) atomicMax(&g_rowmax[m0 + tid], sKey[tid]);
    atomicMax(&g_colmax[n0 + tid], sKey[128 + tid]);
}

// ---------------------------------------------------------------------------
// Kernel 3: fused entropy reduction. 64 blocks produce deterministic partial
// sums; the last-arriving block folds all partials and writes out[0..1].
// ---------------------------------------------------------------------------
__global__ void __launch_bounds__(256) entropy_kernel(float* __restrict__ out)
{
    __shared__ float red[256];
    __shared__ unsigned sLast;
    const int t = threadIdx.x;
    const int i = blockIdx.x * 256 + t;
    const float A = 5.5555555556f;      // 1/(2*sigma^2), sigma=0.3
    const float B = 0.28503426769f;     // -(log(0.3)+0.5*log(2*pi))

    float v = key2f(g_rowmax[i]);
    float d = v - 1.0f;
    float lp = B - A * d * d;
    float s1 = -expf(lp) * lp;

    v = key2f(g_colmax[i]);
    d = v - 1.0f;
    lp = B - A * d * d;
    float s2 = -expf(lp) * lp;

    red[t] = s1; __syncthreads();
    for (int o = 128; o; o >>= 1) { if (t < o) red[t] += red[t + o]; __syncthreads(); }
    if (t == 0) g_part1[blockIdx.x] = red[0];
    __syncthreads();
    red[t] = s2; __syncthreads();
    for (int o = 128; o; o >>= 1) { if (t < o) red[t] += red[t + o]; __syncthreads(); }
    if (t == 0) {
        g_part2[blockIdx.x] = red[0];
        __threadfence();
        sLast = (atomicAdd(&g_ent_ctr, 1u) == ENT_BLOCKS - 1);
    }
    __syncthreads();

    if (sLast) {
        __threadfence();                  // order partial reads after counter
        if (t < 64) {
            const int lid = t & 31;
            float x = (t < 32) ? g_part1[lid] + g_part1[lid + 32]
                               : g_part2[lid] + g_part2[lid + 32];
            #pragma unroll
            for (int o = 16; o; o >>= 1) x += __shfl_xor_sync(0xFFFFFFFFu, x, o);
            if (lid == 0) out[t >> 5] = x;
        }
        if (t == 0) g_ent_ctr = 0u;       // reset for next graph replay
    }
}

extern "C" void kernel_launch(void* const* d_in, const int* in_sizes, int n_in,
                              void* d_out, int out_size)
{
    const float* ex = (const float*)d_in[0];
    const float* ey = (const float*)d_in[1];
    float* out = (float*)d_out;

    cudaFuncSetAttribute(gemm_max_kernel,
                         cudaFuncAttributeMaxDynamicSharedMemorySize, SMEM_TOTAL);

    normalize_kernel<<<(2 * N_ROWS) / 8, 256>>>(ex, ey);
    gemm_max_kernel<<<dim3(N_ROWS / TILE_N, N_ROWS / TILE_M), 256, SMEM_TOTAL>>>();
    entropy_kernel<<<ENT_BLOCKS, 256>>>(out);
}